// round 1
// baseline (speedup 1.0000x reference)
#include <cuda_runtime.h>
#include <cstdint>
#include <cstddef>

#define NB_ROWS 2048
#define NCOMBO  64
#define NSTRUCT 512
#define NHID    1024
#define NITER   60
#define MAXNNZ  (NCOMBO * NSTRUCT)
#define SMNNZ   4096

// ---------------- device scratch (static, allocation-free) ----------------
__device__ float g_C1[NB_ROWS * NHID];
__device__ float g_C2[NB_ROWS * NHID];
__device__ float g_Z [NB_ROWS * NSTRUCT];
__device__ int            g_row_ptr[NCOMBO + 1];
__device__ unsigned short g_csr_cols[MAXNNZ];
__device__ int            g_col_ptr[NSTRUCT + 1];
__device__ unsigned short g_csc_rows[MAXNNZ];
__device__ float g_tau;

// ---------------- prep: build CSR/CSC of S + power iteration -> g_tau ----
__global__ void prep_kernel(const float* __restrict__ S)
{
    __shared__ unsigned char s8[NCOMBO * NSTRUCT];   // 32KB: S as 0/1 bytes
    __shared__ float v[NSTRUCT];
    __shared__ float sv[NCOMBO];
    __shared__ float red[16];
    __shared__ int   scnt[NCOMBO];
    __shared__ int   wtot[16];

    const int t    = threadIdx.x;        // 512 threads
    const int lane = t & 31;
    const int wid  = t >> 5;

    #pragma unroll 4
    for (int i = 0; i < NCOMBO; i++)
        s8[i * NSTRUCT + t] = (S[i * NSTRUCT + t] != 0.0f) ? 1 : 0;
    __syncthreads();

    // ---- CSR (row lists) ----
    if (t < NCOMBO) {
        int c = 0;
        for (int j = 0; j < NSTRUCT; j++) c += s8[t * NSTRUCT + j];
        scnt[t] = c;
    }
    __syncthreads();
    if (t == 0) {
        int acc = 0;
        for (int i = 0; i < NCOMBO; i++) { g_row_ptr[i] = acc; acc += scnt[i]; }
        g_row_ptr[NCOMBO] = acc;
    }
    __syncthreads();
    if (t < NCOMBO) {
        int p = g_row_ptr[t];
        for (int j = 0; j < NSTRUCT; j++)
            if (s8[t * NSTRUCT + j]) g_csr_cols[p++] = (unsigned short)j;
    }

    // ---- CSC (column lists) via block scan over 512 counts ----
    int cc = 0;
    for (int i = 0; i < NCOMBO; i++) cc += s8[i * NSTRUCT + t];
    int incl = cc;
    #pragma unroll
    for (int o = 1; o < 32; o <<= 1) {
        int nbr = __shfl_up_sync(0xffffffffu, incl, o);
        if (lane >= o) incl += nbr;
    }
    if (lane == 31) wtot[wid] = incl;
    __syncthreads();
    if (t < 16) {
        int xv = wtot[t];
        #pragma unroll
        for (int o = 1; o < 16; o <<= 1) {
            int nbr = __shfl_up_sync(0x0000ffffu, xv, o);
            if (t >= o) xv += nbr;
        }
        wtot[t] = xv;
    }
    __syncthreads();
    {
        int base = (wid > 0) ? wtot[wid - 1] : 0;
        int cend = base + incl;              // inclusive -> col_ptr[t+1]
        g_col_ptr[t + 1] = cend;
        if (t == 0) g_col_ptr[0] = 0;
        int p = cend - cc;
        for (int i = 0; i < NCOMBO; i++)
            if (s8[i * NSTRUCT + t]) g_csc_rows[p++] = (unsigned short)i;
    }
    __syncthreads();

    // ---- power iteration on S^T S + I ----
    v[t] = 1.0f / sqrtf((float)NSTRUCT);
    __syncthreads();
    for (int step = 0; step < 30; step++) {
        if (t < NCOMBO) {
            float a = 0.f;
            const int e = g_row_ptr[t + 1];
            for (int p = g_row_ptr[t]; p < e; p++) a += v[g_csr_cols[p]];
            sv[t] = a;
        }
        __syncthreads();
        float w = v[t];
        {
            const int e = g_col_ptr[t + 1];
            for (int p = g_col_ptr[t]; p < e; p++) w += sv[g_csc_rows[p]];
        }
        float sq = w * w;
        #pragma unroll
        for (int o = 16; o > 0; o >>= 1) sq += __shfl_xor_sync(0xffffffffu, sq, o);
        if (lane == 0) red[wid] = sq;
        __syncthreads();
        if (t == 0) {
            float s = 0.f;
            #pragma unroll
            for (int i = 0; i < 16; i++) s += red[i];
            red[0] = sqrtf(s);
        }
        __syncthreads();
        v[t] = w / red[0];
        __syncthreads();
    }
    // L = sqrt(v . (S^T S v + v));  tau = sigma = 0.9/L
    if (t < NCOMBO) {
        float a = 0.f;
        const int e = g_row_ptr[t + 1];
        for (int p = g_row_ptr[t]; p < e; p++) a += v[g_csr_cols[p]];
        sv[t] = a;
    }
    __syncthreads();
    {
        float w = v[t];
        const int e = g_col_ptr[t + 1];
        for (int p = g_col_ptr[t]; p < e; p++) w += sv[g_csc_rows[p]];
        float sq = v[t] * w;
        #pragma unroll
        for (int o = 16; o > 0; o >>= 1) sq += __shfl_xor_sync(0xffffffffu, sq, o);
        if (lane == 0) red[wid] = sq;
        __syncthreads();
        if (t == 0) {
            float s = 0.f;
            #pragma unroll
            for (int i = 0; i < 16; i++) s += red[i];
            g_tau = 0.9f / sqrtf(s);
        }
    }
}

// ---------------- fp32 GEMM + bias + relu (128x128x8, 256 thr, 8x8/thr) --
template<int M, int N, int K>
__device__ __forceinline__ void sgemm_bias_relu(
    const float* __restrict__ A, const float* __restrict__ B,
    const float* __restrict__ bias, float* __restrict__ C)
{
    __shared__ float As[8][128];
    __shared__ float Bs[8][128];
    const int tid  = threadIdx.x;
    const int m0   = blockIdx.y * 128;
    const int n0   = blockIdx.x * 128;
    const int arow = tid >> 1;
    const int acol = (tid & 1) * 4;
    const int brow = tid >> 5;
    const int bcol = (tid & 31) * 4;
    const int tx   = tid & 15;
    const int ty   = tid >> 4;

    float acc[8][8];
    #pragma unroll
    for (int i = 0; i < 8; i++)
        #pragma unroll
        for (int j = 0; j < 8; j++) acc[i][j] = 0.f;

    for (int k0 = 0; k0 < K; k0 += 8) {
        float4 a4 = *(const float4*)(A + (size_t)(m0 + arow) * K + k0 + acol);
        float4 b4 = *(const float4*)(B + (size_t)(k0 + brow) * N + n0 + bcol);
        __syncthreads();
        As[acol + 0][arow] = a4.x;
        As[acol + 1][arow] = a4.y;
        As[acol + 2][arow] = a4.z;
        As[acol + 3][arow] = a4.w;
        *(float4*)&Bs[brow][bcol] = b4;
        __syncthreads();
        #pragma unroll
        for (int kk = 0; kk < 8; kk++) {
            float fa[8], fb[8];
            *(float4*)&fa[0] = *(const float4*)&As[kk][ty * 8];
            *(float4*)&fa[4] = *(const float4*)&As[kk][ty * 8 + 4];
            *(float4*)&fb[0] = *(const float4*)&Bs[kk][tx * 8];
            *(float4*)&fb[4] = *(const float4*)&Bs[kk][tx * 8 + 4];
            #pragma unroll
            for (int i = 0; i < 8; i++)
                #pragma unroll
                for (int j = 0; j < 8; j++)
                    acc[i][j] = fmaf(fa[i], fb[j], acc[i][j]);
        }
    }
    #pragma unroll
    for (int i = 0; i < 8; i++) {
        const int m = m0 + ty * 8 + i;
        #pragma unroll
        for (int j = 0; j < 8; j += 4) {
            const int n = n0 + tx * 8 + j;
            float4 o;
            o.x = fmaxf(acc[i][j + 0] + bias[n + 0], 0.f);
            o.y = fmaxf(acc[i][j + 1] + bias[n + 1], 0.f);
            o.z = fmaxf(acc[i][j + 2] + bias[n + 2], 0.f);
            o.w = fmaxf(acc[i][j + 3] + bias[n + 3], 0.f);
            *(float4*)(C + (size_t)m * N + n) = o;
        }
    }
}

__global__ __launch_bounds__(256) void gemm1_kernel(
    const float* __restrict__ X, const float* __restrict__ W1, const float* __restrict__ b1)
{ sgemm_bias_relu<NB_ROWS, NHID, NCOMBO>(X, W1, b1, g_C1); }

__global__ __launch_bounds__(256) void gemm2_kernel(
    const float* __restrict__ W2, const float* __restrict__ b2)
{ sgemm_bias_relu<NB_ROWS, NHID, NHID>(g_C1, W2, b2, g_C2); }

__global__ __launch_bounds__(256) void gemm3_kernel(
    const float* __restrict__ W3, const float* __restrict__ b3)
{ sgemm_bias_relu<NB_ROWS, NSTRUCT, NHID>(g_C2, W3, b3, g_Z); }

// ---------------- PDHG: 8 batch rows / CTA, 256 threads ------------------
// lane-in-group-of-8 = batch sub-row -> conflict-free smem gathers
__device__ __forceinline__ void pdhg_body(
    const unsigned short* __restrict__ csr,
    const unsigned short* __restrict__ csc,
    const int* __restrict__ rp, const int* __restrict__ cp,
    float* s_xbar, float* s_yhead, float (*s_red)[9], float* s_scale,
    const float* __restrict__ Xg, float* __restrict__ out, const float tau)
{
    const int tid  = threadIdx.x;
    const int b    = tid & 7;      // batch sub-row 0..7
    const int dl   = tid >> 3;     // dim-lane 0..31
    const int lane = tid & 31;
    const int wid  = tid >> 5;
    const int row  = blockIdx.x * 8 + b;

    float x[16], z[16], yt[16], xb[16];
    #pragma unroll
    for (int k = 0; k < 16; k++) {
        const int j = k * 32 + dl;
        z[k]  = g_Z[(size_t)row * NSTRUCT + j];
        x[k]  = 0.f; yt[k] = 0.f; xb[k] = 0.f;
        s_xbar[j * 8 + b] = 0.f;
    }
    const int i0 = dl, i1 = dl + 32;
    const float Bv0 = Xg[(size_t)row * NCOMBO + i0];
    const float Bv1 = Xg[(size_t)row * NCOMBO + i1];
    float yh0 = 0.f, yh1 = 0.f;
    const float sigma = tau;
    const int rp0s = rp[i0], rp0e = rp[i0 + 1];
    const int rp1s = rp[i1], rp1e = rp[i1 + 1];
    __syncthreads();

    for (int it = 0; it < NITER; it++) {
        // ---- y-head: Kx row gathers over CSR ----
        {
            float a = 0.f, a2 = 0.f;
            int p = rp0s;
            for (; p + 1 < rp0e; p += 2) {
                a  += s_xbar[csr[p]     * 8 + b];
                a2 += s_xbar[csr[p + 1] * 8 + b];
            }
            if (p < rp0e) a += s_xbar[csr[p] * 8 + b];
            yh0 = fmaxf(yh0 + sigma * ((a + a2) - Bv0), 0.f);
            s_yhead[i0 * 8 + b] = yh0;
        }
        {
            float a = 0.f, a2 = 0.f;
            int p = rp1s;
            for (; p + 1 < rp1e; p += 2) {
                a  += s_xbar[csr[p]     * 8 + b];
                a2 += s_xbar[csr[p + 1] * 8 + b];
            }
            if (p < rp1e) a += s_xbar[csr[p] * 8 + b];
            yh1 = fmaxf(yh1 + sigma * ((a + a2) - Bv1), 0.f);
            s_yhead[i1 * 8 + b] = yh1;
        }
        // ---- y-tail (elementwise, register-resident) ----
        #pragma unroll
        for (int k = 0; k < 16; k++)
            yt[k] = fmaxf(yt[k] - sigma * xb[k], 0.f);
        __syncthreads();

        // ---- KTy column gathers over CSC + prox residual ----
        float ss = 0.f;
        float d[16];
        #pragma unroll
        for (int k = 0; k < 16; k++) {
            const int j = k * 32 + dl;
            float tj = -yt[k];
            const int e = cp[j + 1];
            for (int p = cp[j]; p < e; p++)
                tj += s_yhead[csc[p] * 8 + b];
            const float dd = (x[k] - tau * tj) + tau - z[k];
            d[k] = dd;
            ss += dd * dd;
        }
        // reduce ||d||^2 per batch row b (lanes with same (tid&7))
        ss += __shfl_xor_sync(0xffffffffu, ss, 8);
        ss += __shfl_xor_sync(0xffffffffu, ss, 16);
        if (lane < 8) s_red[wid][lane] = ss;
        __syncthreads();
        if (tid < 8) {
            float tot = 0.f;
            #pragma unroll
            for (int w = 0; w < 8; w++) tot += s_red[w][tid];
            const float nrm = sqrtf(tot);
            s_scale[tid] = fmaxf(1.f - tau / fmaxf(nrm, 1e-12f), 0.f);
        }
        __syncthreads();
        const float sc = s_scale[b];
        #pragma unroll
        for (int k = 0; k < 16; k++) {
            const float xn  = z[k] + sc * d[k];
            const float xbn = 2.f * xn - x[k];
            x[k] = xn; xb[k] = xbn;
            s_xbar[(k * 32 + dl) * 8 + b] = xbn;
        }
        __syncthreads();
    }
    #pragma unroll
    for (int k = 0; k < 16; k++)
        out[(size_t)row * NSTRUCT + k * 32 + dl] = x[k];
}

__global__ __launch_bounds__(256) void pdhg_kernel(
    const float* __restrict__ Xg, float* __restrict__ out)
{
    __shared__ float s_xbar[NSTRUCT * 8];      // 16KB   layout [j][b]
    __shared__ float s_yhead[NCOMBO * 8];      // 2KB    layout [i][b]
    __shared__ unsigned short s_csr[SMNNZ];    // 8KB
    __shared__ unsigned short s_csc[SMNNZ];    // 8KB
    __shared__ int   s_rp[NCOMBO + 1];
    __shared__ int   s_cp[NSTRUCT + 1];
    __shared__ float s_red[8][9];
    __shared__ float s_scale[8];

    const int tid = threadIdx.x;
    for (int p = tid; p < NCOMBO + 1; p += 256)  s_rp[p] = g_row_ptr[p];
    for (int p = tid; p < NSTRUCT + 1; p += 256) s_cp[p] = g_col_ptr[p];
    __syncthreads();
    const int nnz = s_rp[NCOMBO];
    const float tau = g_tau;

    if (nnz <= SMNNZ) {
        for (int p = tid; p < nnz; p += 256) {
            s_csr[p] = g_csr_cols[p];
            s_csc[p] = g_csc_rows[p];
        }
        __syncthreads();
        pdhg_body(s_csr, s_csc, s_rp, s_cp, s_xbar, s_yhead, s_red, s_scale, Xg, out, tau);
    } else {
        pdhg_body(g_csr_cols, g_csc_rows, s_rp, s_cp, s_xbar, s_yhead, s_red, s_scale, Xg, out, tau);
    }
}

// ---------------- launch -------------------------------------------------
extern "C" void kernel_launch(void* const* d_in, const int* in_sizes, int n_in,
                              void* d_out, int out_size)
{
    const float* X  = (const float*)d_in[0];
    const float* W1 = (const float*)d_in[1];
    const float* b1 = (const float*)d_in[2];
    const float* W2 = (const float*)d_in[3];
    const float* b2 = (const float*)d_in[4];
    const float* W3 = (const float*)d_in[5];
    const float* b3 = (const float*)d_in[6];
    const float* S  = (const float*)d_in[7];
    float* out = (float*)d_out;

    prep_kernel<<<1, 512>>>(S);

    gemm1_kernel<<<dim3(NHID / 128,    NB_ROWS / 128), 256>>>(X, W1, b1);
    gemm2_kernel<<<dim3(NHID / 128,    NB_ROWS / 128), 256>>>(W2, b2);
    gemm3_kernel<<<dim3(NSTRUCT / 128, NB_ROWS / 128), 256>>>(W3, b3);

    pdhg_kernel<<<NB_ROWS / 8, 256>>>(X, out);
}

// round 2
// speedup vs baseline: 1.3420x; 1.3420x over previous
#include <cuda_runtime.h>
#include <cstdint>
#include <cstddef>

#define NB_ROWS 2048
#define NCOMBO  64
#define NSTRUCT 512
#define NHID    1024
#define NITER   60
#define MAXNNZ  (NCOMBO * NSTRUCT)
#define SMNNZ   4096

// ---------------- device scratch (static, allocation-free) ----------------
__device__ float g_C1[NB_ROWS * NHID];
__device__ float g_C2[NB_ROWS * NHID];
__device__ float g_Z [NB_ROWS * NSTRUCT];
__device__ int            g_row_ptr[NCOMBO + 1];
__device__ unsigned short g_csr_cols[MAXNNZ];
__device__ int            g_col_ptr[NSTRUCT + 1];
__device__ unsigned short g_csc_rows[MAXNNZ];
__device__ float g_tau;

// ---------------- cp.async helpers ---------------------------------------
__device__ __forceinline__ void cp_async16(void* smem, const void* gmem) {
    unsigned s = (unsigned)__cvta_generic_to_shared(smem);
    asm volatile("cp.async.cg.shared.global [%0], [%1], 16;\n" :: "r"(s), "l"(gmem));
}
__device__ __forceinline__ void cp_commit() {
    asm volatile("cp.async.commit_group;\n");
}
template<int N_> __device__ __forceinline__ void cp_wait() {
    asm volatile("cp.async.wait_group %0;\n" :: "n"(N_));
}

// ---------------- prep: build CSR/CSC of S + power iteration -> g_tau ----
__global__ void prep_kernel(const float* __restrict__ S)
{
    __shared__ unsigned char s8[NCOMBO * NSTRUCT];   // 32KB: S as 0/1 bytes
    __shared__ float v[NSTRUCT];
    __shared__ float sv[NCOMBO];
    __shared__ float red[16];
    __shared__ int   scnt[NCOMBO];
    __shared__ int   wtot[16];

    const int t    = threadIdx.x;        // 512 threads
    const int lane = t & 31;
    const int wid  = t >> 5;

    #pragma unroll 4
    for (int i = 0; i < NCOMBO; i++)
        s8[i * NSTRUCT + t] = (S[i * NSTRUCT + t] != 0.0f) ? 1 : 0;
    __syncthreads();

    // ---- CSR (row lists) ----
    if (t < NCOMBO) {
        int c = 0;
        for (int j = 0; j < NSTRUCT; j++) c += s8[t * NSTRUCT + j];
        scnt[t] = c;
    }
    __syncthreads();
    if (t == 0) {
        int acc = 0;
        for (int i = 0; i < NCOMBO; i++) { g_row_ptr[i] = acc; acc += scnt[i]; }
        g_row_ptr[NCOMBO] = acc;
    }
    __syncthreads();
    if (t < NCOMBO) {
        int p = g_row_ptr[t];
        for (int j = 0; j < NSTRUCT; j++)
            if (s8[t * NSTRUCT + j]) g_csr_cols[p++] = (unsigned short)j;
    }

    // ---- CSC (column lists) via block scan over 512 counts ----
    int cc = 0;
    for (int i = 0; i < NCOMBO; i++) cc += s8[i * NSTRUCT + t];
    int incl = cc;
    #pragma unroll
    for (int o = 1; o < 32; o <<= 1) {
        int nbr = __shfl_up_sync(0xffffffffu, incl, o);
        if (lane >= o) incl += nbr;
    }
    if (lane == 31) wtot[wid] = incl;
    __syncthreads();
    if (t < 16) {
        int xv = wtot[t];
        #pragma unroll
        for (int o = 1; o < 16; o <<= 1) {
            int nbr = __shfl_up_sync(0x0000ffffu, xv, o);
            if (t >= o) xv += nbr;
        }
        wtot[t] = xv;
    }
    __syncthreads();
    {
        int base = (wid > 0) ? wtot[wid - 1] : 0;
        int cend = base + incl;              // inclusive -> col_ptr[t+1]
        g_col_ptr[t + 1] = cend;
        if (t == 0) g_col_ptr[0] = 0;
        int p = cend - cc;
        for (int i = 0; i < NCOMBO; i++)
            if (s8[i * NSTRUCT + t]) g_csc_rows[p++] = (unsigned short)i;
    }
    __syncthreads();

    // ---- power iteration on S^T S + I ----
    v[t] = 1.0f / sqrtf((float)NSTRUCT);
    __syncthreads();
    for (int step = 0; step < 30; step++) {
        if (t < NCOMBO) {
            float a = 0.f;
            const int e = g_row_ptr[t + 1];
            for (int p = g_row_ptr[t]; p < e; p++) a += v[g_csr_cols[p]];
            sv[t] = a;
        }
        __syncthreads();
        float w = v[t];
        {
            const int e = g_col_ptr[t + 1];
            for (int p = g_col_ptr[t]; p < e; p++) w += sv[g_csc_rows[p]];
        }
        float sq = w * w;
        #pragma unroll
        for (int o = 16; o > 0; o >>= 1) sq += __shfl_xor_sync(0xffffffffu, sq, o);
        if (lane == 0) red[wid] = sq;
        __syncthreads();
        if (t == 0) {
            float s = 0.f;
            #pragma unroll
            for (int i = 0; i < 16; i++) s += red[i];
            red[0] = sqrtf(s);
        }
        __syncthreads();
        v[t] = w / red[0];
        __syncthreads();
    }
    // L = sqrt(v . (S^T S v + v));  tau = sigma = 0.9/L
    if (t < NCOMBO) {
        float a = 0.f;
        const int e = g_row_ptr[t + 1];
        for (int p = g_row_ptr[t]; p < e; p++) a += v[g_csr_cols[p]];
        sv[t] = a;
    }
    __syncthreads();
    {
        float w = v[t];
        const int e = g_col_ptr[t + 1];
        for (int p = g_col_ptr[t]; p < e; p++) w += sv[g_csc_rows[p]];
        float sq = v[t] * w;
        #pragma unroll
        for (int o = 16; o > 0; o >>= 1) sq += __shfl_xor_sync(0xffffffffu, sq, o);
        if (lane == 0) red[wid] = sq;
        __syncthreads();
        if (t == 0) {
            float s = 0.f;
            #pragma unroll
            for (int i = 0; i < 16; i++) s += red[i];
            g_tau = 0.9f / sqrtf(s);
        }
    }
}

// ---------------- fp32 GEMM + bias + relu, cp.async double-buffered ------
// Tile BM x BN, KC=16, THREADS = (BM/8)*(BN/8). Microtile 8x8 per thread,
// arranged as 2 row-spans (ty*4, ty*4+BM/2) x 2 col-spans (tx*4, tx*4+BN/2)
// => B fragment loads are two LDS.128 at tx*4: banks {0,4,...,28}, conflict-free.
template<int BM, int BN, int THREADS, int K, int N>
__device__ __forceinline__ void sgemm_v2(
    const float* __restrict__ A, const float* __restrict__ B,
    const float* __restrict__ bias, float* __restrict__ C)
{
    constexpr int KC = 16;
    constexpr int CA = BM * KC / 4;
    constexpr int CB = KC * BN / 4;
    constexpr int NSTAGE = K / KC;
    __shared__ float As[2][BM][KC];
    __shared__ float Bs[2][KC][BN];

    const int tid = threadIdx.x;
    const int m0  = blockIdx.y * BM;
    const int n0  = blockIdx.x * BN;
    constexpr int TX = BN / 8;
    const int tx = tid % TX;
    const int ty = tid / TX;
    const int rowA = ty * 4;
    const int colA = tx * 4;

    float acc[8][8];
    #pragma unroll
    for (int i = 0; i < 8; i++)
        #pragma unroll
        for (int j = 0; j < 8; j++) acc[i][j] = 0.f;

    // prologue: stage 0
    {
        #pragma unroll
        for (int c = tid; c < CA; c += THREADS) {
            int m  = c >> 2;
            int kq = (c & 3) * 4;
            cp_async16(&As[0][m][kq], A + (size_t)(m0 + m) * K + kq);
        }
        #pragma unroll
        for (int c = tid; c < CB; c += THREADS) {
            int kr = c / (BN / 4);
            int nq = (c % (BN / 4)) * 4;
            cp_async16(&Bs[0][kr][nq], B + (size_t)kr * N + n0 + nq);
        }
        cp_commit();
    }

    for (int s = 0; s < NSTAGE; s++) {
        if (s + 1 < NSTAGE) {
            const int k0 = (s + 1) * KC;
            const int nb = (s + 1) & 1;
            #pragma unroll
            for (int c = tid; c < CA; c += THREADS) {
                int m  = c >> 2;
                int kq = (c & 3) * 4;
                cp_async16(&As[nb][m][kq], A + (size_t)(m0 + m) * K + k0 + kq);
            }
            #pragma unroll
            for (int c = tid; c < CB; c += THREADS) {
                int kr = c / (BN / 4);
                int nq = (c % (BN / 4)) * 4;
                cp_async16(&Bs[nb][kr][nq], B + (size_t)(k0 + kr) * N + n0 + nq);
            }
            cp_commit();
            cp_wait<1>();
        } else {
            cp_wait<0>();
        }
        __syncthreads();
        const int buf = s & 1;
        #pragma unroll
        for (int kk = 0; kk < KC; kk++) {
            float fa[8], fb[8];
            #pragma unroll
            for (int i = 0; i < 4; i++) {
                fa[i]     = As[buf][rowA + i][kk];
                fa[4 + i] = As[buf][rowA + BM / 2 + i][kk];
            }
            *(float4*)&fb[0] = *(const float4*)&Bs[buf][kk][colA];
            *(float4*)&fb[4] = *(const float4*)&Bs[buf][kk][colA + BN / 2];
            #pragma unroll
            for (int i = 0; i < 8; i++)
                #pragma unroll
                for (int j = 0; j < 8; j++)
                    acc[i][j] = fmaf(fa[i], fb[j], acc[i][j]);
        }
        __syncthreads();
    }

    // epilogue: bias + relu, float4 stores
    float4 bl = *(const float4*)(bias + n0 + colA);
    float4 bh = *(const float4*)(bias + n0 + colA + BN / 2);
    #pragma unroll
    for (int half = 0; half < 2; half++) {
        #pragma unroll
        for (int i = 0; i < 4; i++) {
            const int m  = m0 + rowA + half * (BM / 2) + i;
            const int ai = half * 4 + i;
            float4 o;
            o.x = fmaxf(acc[ai][0] + bl.x, 0.f);
            o.y = fmaxf(acc[ai][1] + bl.y, 0.f);
            o.z = fmaxf(acc[ai][2] + bl.z, 0.f);
            o.w = fmaxf(acc[ai][3] + bl.w, 0.f);
            *(float4*)(C + (size_t)m * N + n0 + colA) = o;
            float4 p;
            p.x = fmaxf(acc[ai][4] + bh.x, 0.f);
            p.y = fmaxf(acc[ai][5] + bh.y, 0.f);
            p.z = fmaxf(acc[ai][6] + bh.z, 0.f);
            p.w = fmaxf(acc[ai][7] + bh.w, 0.f);
            *(float4*)(C + (size_t)m * N + n0 + colA + BN / 2) = p;
        }
    }
}

__global__ __launch_bounds__(256, 2) void gemm1_kernel(
    const float* __restrict__ X, const float* __restrict__ W1, const float* __restrict__ b1)
{ sgemm_v2<128, 128, 256, NCOMBO, NHID>(X, W1, b1, g_C1); }

__global__ __launch_bounds__(256, 2) void gemm2_kernel(
    const float* __restrict__ W2, const float* __restrict__ b2)
{ sgemm_v2<128, 128, 256, NHID, NHID>(g_C1, W2, b2, g_C2); }

__global__ __launch_bounds__(128, 2) void gemm3_kernel(
    const float* __restrict__ W3, const float* __restrict__ b3)
{ sgemm_v2<64, 128, 128, NHID, NSTRUCT>(g_C2, W3, b3, g_Z); }

// ---------------- PDHG v2: 8 batch rows / CTA, float2 over batch ----------
// thread = (dl 0..63, b2 0..3). Each thread owns 2 batch rows (float2) and
// 8 x-columns (j = k*64+dl), plus head row i = dl. 3 barriers / iteration.
__global__ __launch_bounds__(256, 2) void pdhg_kernel(
    const float* __restrict__ Xg, float* __restrict__ out)
{
    __shared__ float s_xbar[NSTRUCT * 8];        // 16KB  [j][batch8]
    __shared__ float s_yhead[NCOMBO * 8];        // 2KB   [i][batch8]
    __shared__ unsigned short s_csr[SMNNZ];      // 8KB
    __shared__ unsigned short s_csc[SMNNZ];      // 8KB
    __shared__ int    s_rp[NCOMBO + 1];
    __shared__ int    s_cp[NSTRUCT + 1];
    __shared__ float2 s_red[8][4];

    const int tid = threadIdx.x;
    const int b2  = tid & 3;        // batch pair 0..3
    const int dl  = tid >> 2;       // dim lane 0..63
    const int wid = tid >> 5;
    const int r0  = blockIdx.x * 8 + b2 * 2;

    for (int p = tid; p < NCOMBO + 1;  p += 256) s_rp[p] = g_row_ptr[p];
    for (int p = tid; p < NSTRUCT + 1; p += 256) s_cp[p] = g_col_ptr[p];
    __syncthreads();
    const int nnz = s_rp[NCOMBO];
    for (int p = tid; p < nnz && p < SMNNZ; p += 256) {
        s_csr[p] = g_csr_cols[p];
        s_csc[p] = g_csc_rows[p];
    }
    const unsigned short* __restrict__ csr = (nnz <= SMNNZ) ? s_csr : g_csr_cols;
    const unsigned short* __restrict__ csc = (nnz <= SMNNZ) ? s_csc : g_csc_rows;
    const float tau = g_tau;

    float2 x[8], z[8], yt[8], xb[8];
    #pragma unroll
    for (int k = 0; k < 8; k++) {
        const int j = k * 64 + dl;
        z[k].x = g_Z[(size_t)r0 * NSTRUCT + j];
        z[k].y = g_Z[(size_t)(r0 + 1) * NSTRUCT + j];
        x[k]  = make_float2(0.f, 0.f);
        yt[k] = make_float2(0.f, 0.f);
        xb[k] = make_float2(0.f, 0.f);
        *(float2*)&s_xbar[j * 8 + b2 * 2] = make_float2(0.f, 0.f);
    }
    const int i = dl;
    float2 Bv = make_float2(Xg[(size_t)r0 * NCOMBO + i],
                            Xg[(size_t)(r0 + 1) * NCOMBO + i]);
    float2 yh = make_float2(0.f, 0.f);
    const int rs = s_rp[i], re = s_rp[i + 1];
    __syncthreads();

    for (int it = 0; it < NITER; it++) {
        // ---- phase A: y-head (Kx over CSR) + y-tail ----
        float2 a = make_float2(0.f, 0.f);
        for (int p = rs; p < re; p++) {
            float2 v = *(const float2*)&s_xbar[csr[p] * 8 + b2 * 2];
            a.x += v.x; a.y += v.y;
        }
        yh.x = fmaxf(yh.x + tau * (a.x - Bv.x), 0.f);
        yh.y = fmaxf(yh.y + tau * (a.y - Bv.y), 0.f);
        *(float2*)&s_yhead[i * 8 + b2 * 2] = yh;
        #pragma unroll
        for (int k = 0; k < 8; k++) {
            yt[k].x = fmaxf(yt[k].x - tau * xb[k].x, 0.f);
            yt[k].y = fmaxf(yt[k].y - tau * xb[k].y, 0.f);
        }
        __syncthreads();

        // ---- phase B: KTy over CSC + prox residual ----
        float2 d[8];
        float ssx = 0.f, ssy = 0.f;
        #pragma unroll
        for (int k = 0; k < 8; k++) {
            const int j = k * 64 + dl;
            float tvx = -yt[k].x, tvy = -yt[k].y;
            const int e = s_cp[j + 1];
            for (int p = s_cp[j]; p < e; p++) {
                float2 v = *(const float2*)&s_yhead[csc[p] * 8 + b2 * 2];
                tvx += v.x; tvy += v.y;
            }
            const float dx = x[k].x - tau * tvx + tau - z[k].x;
            const float dy = x[k].y - tau * tvy + tau - z[k].y;
            d[k] = make_float2(dx, dy);
            ssx += dx * dx;
            ssy += dy * dy;
        }
        // reduce over dl within warp (lanes differing in dl bits only)
        ssx += __shfl_xor_sync(0xffffffffu, ssx, 4);
        ssy += __shfl_xor_sync(0xffffffffu, ssy, 4);
        ssx += __shfl_xor_sync(0xffffffffu, ssx, 8);
        ssy += __shfl_xor_sync(0xffffffffu, ssy, 8);
        ssx += __shfl_xor_sync(0xffffffffu, ssx, 16);
        ssy += __shfl_xor_sync(0xffffffffu, ssy, 16);
        if ((tid & 31) < 4) s_red[wid][b2] = make_float2(ssx, ssy);
        __syncthreads();

        // ---- phase C: scale + x/xbar update ----
        float totx = 0.f, toty = 0.f;
        #pragma unroll
        for (int w = 0; w < 8; w++) {
            float2 r = s_red[w][b2];
            totx += r.x; toty += r.y;
        }
        const float scx = fmaxf(1.f - tau / fmaxf(sqrtf(totx), 1e-12f), 0.f);
        const float scy = fmaxf(1.f - tau / fmaxf(sqrtf(toty), 1e-12f), 0.f);
        #pragma unroll
        for (int k = 0; k < 8; k++) {
            const float xnx = z[k].x + scx * d[k].x;
            const float xny = z[k].y + scy * d[k].y;
            float2 xbn = make_float2(2.f * xnx - x[k].x, 2.f * xny - x[k].y);
            x[k]  = make_float2(xnx, xny);
            xb[k] = xbn;
            *(float2*)&s_xbar[(k * 64 + dl) * 8 + b2 * 2] = xbn;
        }
        __syncthreads();
    }

    #pragma unroll
    for (int k = 0; k < 8; k++) {
        const int j = k * 64 + dl;
        out[(size_t)r0 * NSTRUCT + j]       = x[k].x;
        out[(size_t)(r0 + 1) * NSTRUCT + j] = x[k].y;
    }
}

// ---------------- launch -------------------------------------------------
extern "C" void kernel_launch(void* const* d_in, const int* in_sizes, int n_in,
                              void* d_out, int out_size)
{
    const float* X  = (const float*)d_in[0];
    const float* W1 = (const float*)d_in[1];
    const float* b1 = (const float*)d_in[2];
    const float* W2 = (const float*)d_in[3];
    const float* b2 = (const float*)d_in[4];
    const float* W3 = (const float*)d_in[5];
    const float* b3 = (const float*)d_in[6];
    const float* S  = (const float*)d_in[7];
    float* out = (float*)d_out;

    prep_kernel<<<1, 512>>>(S);

    gemm1_kernel<<<dim3(NHID / 128,    NB_ROWS / 128), 256>>>(X, W1, b1);
    gemm2_kernel<<<dim3(NHID / 128,    NB_ROWS / 128), 256>>>(W2, b2);
    gemm3_kernel<<<dim3(NSTRUCT / 128, NB_ROWS / 64),  128>>>(W3, b3);

    pdhg_kernel<<<NB_ROWS / 8, 256>>>(X, out);
}